// round 15
// baseline (speedup 1.0000x reference)
#include <cuda_runtime.h>
#include <math.h>

// ---------------------------------------------------------------------------
// VQ-VAE 3D forward (R15): row-wise conv processing (tiny per-thread state ->
// 2+ blocks/SM), COVEC=4 on enc1/enc2 (half the input passes), launch_bounds.
//   enc: conv(1->16,k4s2p1)+relu -> conv(16->32)+relu -> conv(32->64) = z_e
//   vq : nearest codebook entry (512x64), quantized = codebook[argmin]
//   dec: convT(64->32)+relu -> convT(32->16)+relu -> convT(16->1)+sigmoid
// Output layout in d_out (float): [x_hat (4*1*128^3) | quantized | z_e]
// ---------------------------------------------------------------------------

typedef unsigned long long u64;

__device__ __forceinline__ u64 pk2(float lo, float hi) {
    u64 r; asm("mov.b64 %0, {%1, %2};" : "=l"(r) : "f"(lo), "f"(hi)); return r;
}
__device__ __forceinline__ u64 dup2(float v) { return pk2(v, v); }
__device__ __forceinline__ void fma2(u64& d, u64 a, u64 b) {
    asm("fma.rn.f32x2 %0, %1, %2, %0;" : "+l"(d) : "l"(a), "l"(b));
}
__device__ __forceinline__ void up2(u64 v, float& a, float& b) {
    asm("mov.b64 {%0, %1}, %2;" : "=f"(a), "=f"(b) : "l"(v));
}

// scratch (no allocations allowed) -- reused across stages
__device__ __align__(16) float g_h1[4 * 16 * 64 * 64 * 64]; // conv1 out / dec2 out
__device__ __align__(16) float g_h2[4 * 32 * 32 * 32 * 32]; // conv2 out / dec1 out

// ===========================================================================
// Strided conv3d, k=4 s=2 p=1. One thread = 2(od) x 2(oh) x 4(ow) outputs x
// COVEC channels (channel-paired f32x2 accumulators, CP = COVEC/2).
// ROW-WISE: only one 10-col dup-packed input row is live at a time.
// Row (u, v) feeds rd with a_d = u-2rd in [0,4) and rh with ah = v-2rh in
// [0,4). Input col for (rw, aw) is R[2*rw + aw].
// Row load: 2 aligned float4; edge cols via neighbor-lane shfl (BQ | 32, and
// shfl-invalid lanes are exactly the zero-padded ones).
// ACT: 0 none, 1 relu
// ===========================================================================
template <int CIN, int COVEC, int ACT>
__global__ void __launch_bounds__(256, 2)
conv_s2_blk(const float* __restrict__ x,
            const float* __restrict__ w,   // [Cout][CIN][4][4][4]
            const float* __restrict__ bias,
            float* __restrict__ y,
            int Din, int Dout, int Cout)
{
    static_assert(COVEC % 2 == 0, "COVEC even");
    constexpr int CP = COVEC / 2;
    extern __shared__ float ws[]; // [CIN*64][COVEC] interleaved
    const int co0 = blockIdx.y * COVEC;
    const int n   = blockIdx.z;

    const int WTOT = CIN * 64 * COVEC;
    for (int e = threadIdx.x; e < WTOT; e += blockDim.x) {
        int c  = e % COVEC;
        int r  = e / COVEC;          // ci*64 + tap
        int ci = r >> 6, t = r & 63;
        ws[e] = w[((co0 + c) * CIN + ci) * 64 + t];
    }
    __syncthreads();

    const int B   = Dout >> 1;  // oh/od bases
    const int BQ  = Dout >> 2;  // ow quads (4 | BQ | 32 for all layers)
    const int pos = blockIdx.x * blockDim.x + threadIdx.x;
    const int bq = pos % BQ;
    const int bh = (pos / BQ) % B;
    const int bd = pos / (BQ * B);

    const int zb = 4 * bd - 1, yb = 4 * bh - 1, xb0 = 8 * bq - 1;
    bool pz[6], py[6];
#pragma unroll
    for (int u = 0; u < 6; u++) {
        pz[u] = (unsigned)(zb + u) < (unsigned)Din;
        py[u] = (unsigned)(yb + u) < (unsigned)Din;
    }
    const bool px0 = (bq > 0);
    const bool px9 = (bq < BQ - 1);

    u64 acc[16 * CP]; // [((rd*2+rh)*4 + rw) * CP + c]
#pragma unroll
    for (int o = 0; o < 16; o++)
#pragma unroll
        for (int c = 0; c < CP; c++)
            acc[o * CP + c] = pk2(bias[co0 + 2 * c], bias[co0 + 2 * c + 1]);

    const int DIN2 = Din * Din;
    const float* xn = x + (size_t)n * CIN * Din * DIN2;

    for (int ci = 0; ci < CIN; ci++) {
        const float* xc = xn + (size_t)ci * Din * DIN2 + yb * Din + xb0;
        const float* wc = ws + ci * 64 * COVEC;
#pragma unroll
        for (int u = 0; u < 6; u++) {
#pragma unroll
            for (int v = 0; v < 6; v++) {
                // ---- load row (z = zb+u, y = yb+v), dup-packed ----
                const bool pr = pz[u] && py[v];
                const float* row = xc + (zb + u) * DIN2 + v * Din;
                float4 fa = pr ? __ldg((const float4*)(row + 1))
                               : make_float4(0.f, 0.f, 0.f, 0.f);
                float4 fb = pr ? __ldg((const float4*)(row + 5))
                               : make_float4(0.f, 0.f, 0.f, 0.f);
                float x0s = __shfl_up_sync(0xffffffffu, fb.w, 1);   // col 8bq-1
                float x9s = __shfl_down_sync(0xffffffffu, fa.x, 1); // col 8bq+8
                u64 R[10];
                R[0] = dup2((pr && px0) ? x0s : 0.f);
                R[1] = dup2(fa.x); R[2] = dup2(fa.y);
                R[3] = dup2(fa.z); R[4] = dup2(fa.w);
                R[5] = dup2(fb.x); R[6] = dup2(fb.y);
                R[7] = dup2(fb.z); R[8] = dup2(fb.w);
                R[9] = dup2((pr && px9) ? x9s : 0.f);

                // ---- consume row ----
#pragma unroll
                for (int rd = 0; rd < 2; rd++) {
                    const int a_d = u - 2 * rd;
                    if (a_d < 0 || a_d > 3) continue;   // compile-time
#pragma unroll
                    for (int rh = 0; rh < 2; rh++) {
                        const int ah = v - 2 * rh;
                        if (ah < 0 || ah > 3) continue; // compile-time
                        const float* wt = wc + (a_d * 16 + ah * 4) * COVEC;
                        const int o = (rd * 2 + rh) * 4;
                        if (CP == 2) {
#pragma unroll
                            for (int aw = 0; aw < 4; aw++) {
                                const ulonglong2 wq =
                                    *(const ulonglong2*)(wt + aw * COVEC);
#pragma unroll
                                for (int rw = 0; rw < 4; rw++) {
                                    fma2(acc[(o + rw) * 2 + 0], R[2 * rw + aw], wq.x);
                                    fma2(acc[(o + rw) * 2 + 1], R[2 * rw + aw], wq.y);
                                }
                            }
                        } else { // CP == 1: two taps per LDS.128
#pragma unroll
                            for (int awp = 0; awp < 2; awp++) {
                                const ulonglong2 wq =
                                    *(const ulonglong2*)(wt + awp * 2 * COVEC);
#pragma unroll
                                for (int rw = 0; rw < 4; rw++) {
                                    fma2(acc[o + rw], R[2 * rw + 2 * awp],     wq.x);
                                    fma2(acc[o + rw], R[2 * rw + 2 * awp + 1], wq.y);
                                }
                            }
                        }
                    }
                }
            }
        }
    }

    const int OUT2 = Dout * Dout;
    const size_t OUT3 = (size_t)OUT2 * Dout;
    float* yo = y + ((size_t)(n * Cout + co0) * Dout + 2 * bd) * OUT2
                  + (2 * bh) * Dout + 4 * bq;
#pragma unroll
    for (int c = 0; c < CP; c++) {
#pragma unroll
        for (int rd = 0; rd < 2; rd++)
#pragma unroll
            for (int rh = 0; rh < 2; rh++) {
                float lo[4], hi[4];
#pragma unroll
                for (int rw = 0; rw < 4; rw++) {
                    up2(acc[((rd * 2 + rh) * 4 + rw) * CP + c], lo[rw], hi[rw]);
                    if (ACT == 1) { lo[rw] = fmaxf(lo[rw], 0.f); hi[rw] = fmaxf(hi[rw], 0.f); }
                }
                float* p0 = yo + (size_t)(2 * c) * OUT3 + rd * OUT2 + rh * Dout;
                *(float4*)p0          = make_float4(lo[0], lo[1], lo[2], lo[3]);
                *(float4*)(p0 + OUT3) = make_float4(hi[0], hi[1], hi[2], hi[3]);
            }
    }
}

// ===========================================================================
// Transposed conv3d, k=4 s=2 p=1. One thread = TWO adjacent w input-bases ->
// 2(od) x 2(oh) x 4(ow) outputs x COVEC channels (channel-paired f32x2).
// ROW-WISE: one 4-col dup-packed row live at a time. tap t -> (r, delta):
// t=0:(1,+1) t=1:(0,0) t=2:(1,0) t=3:(0,-1); dz=(r+3-t)>>1, so
// dz=0:{t3}, dz=1:{t1,t2}, dz=2:{t0} (same for dy/th).
// Weights: PyTorch ConvTranspose layout [CIN][Cout][4][4][4].
// ACT: 0 none, 1 relu
// ===========================================================================
template <int CIN, int COVEC, int ACT>
__global__ void __launch_bounds__(256, 2)
convT_blk(const float* __restrict__ x,
          const float* __restrict__ w,
          const float* __restrict__ bias,
          float* __restrict__ y,
          int In, int Out, int Cout)
{
    static_assert(COVEC % 2 == 0, "COVEC even");
    constexpr int CP = COVEC / 2;
    extern __shared__ float ws[]; // [CIN*64][COVEC]
    const int co0 = blockIdx.y * COVEC;
    const int n   = blockIdx.z;

    const int WTOT = CIN * 64 * COVEC;
    for (int e = threadIdx.x; e < WTOT; e += blockDim.x) {
        int c  = e % COVEC;
        int r  = e / COVEC;
        int ci = r >> 6, t = r & 63;
        ws[e] = w[((size_t)ci * Cout + co0 + c) * 64 + t];
    }
    __syncthreads();

    const int BQ  = In >> 1; // w base-pairs per dim (divides 32)
    const int pos = blockIdx.x * blockDim.x + threadIdx.x;
    const int bq = pos % BQ;
    const int bh = (pos / BQ) % In;
    const int bd = pos / (BQ * In);
    const int bw0 = 2 * bq;

    bool pd[3], ph[3];
    pd[0] = (bd > 0); pd[1] = true; pd[2] = (bd < In - 1);
    ph[0] = (bh > 0); ph[1] = true; ph[2] = (bh < In - 1);
    const bool pc0 = (bq > 0);
    const bool pc3 = (bq < BQ - 1);

    u64 acc[16 * CP]; // [((rd*2+rh)*4 + (2*beta+rw)) * CP + c]
#pragma unroll
    for (int o = 0; o < 16; o++)
#pragma unroll
        for (int c = 0; c < CP; c++)
            acc[o * CP + c] = pk2(bias[co0 + 2 * c], bias[co0 + 2 * c + 1]);

    // tap lists per cube plane: dz=0:{t3}, dz=1:{t1,t2}, dz=2:{t0}
    const int TDL[3][2] = {{3, 0}, {1, 2}, {0, 0}};
    const int TDN[3]    = {1, 2, 1};

    const int IN2 = In * In;
    const size_t IN3 = (size_t)IN2 * In;
    const float* xn = x + (size_t)n * CIN * IN3;

    for (int ci = 0; ci < CIN; ci++) {
        const float* xc = xn + ci * IN3 + (bh - 1) * In + (bw0 - 1);
        const float* wc = ws + ci * 64 * COVEC;
#pragma unroll
        for (int dz = 0; dz < 3; dz++) {
#pragma unroll
            for (int dy = 0; dy < 3; dy++) {
                // ---- load row (4 cols), dup-packed ----
                const bool pr = pd[dz] && ph[dy];
                const float* row = xc + (bd + dz - 1) * IN2 + dy * In;
                float2 f2 = pr ? __ldg((const float2*)(row + 1)) : make_float2(0.f, 0.f);
                float c0s = __shfl_up_sync(0xffffffffu, f2.y, 1);   // col bw0-1
                float c3s = __shfl_down_sync(0xffffffffu, f2.x, 1); // col bw0+2
                u64 Xe[4];
                Xe[0] = dup2((pr && pc0) ? c0s : 0.f);
                Xe[1] = dup2(f2.x);
                Xe[2] = dup2(f2.y);
                Xe[3] = dup2((pr && pc3) ? c3s : 0.f);

                // ---- consume row ----
#pragma unroll
                for (int i = 0; i < 2; i++) {
                    if (i >= TDN[dz]) continue;      // compile-time
                    const int td = TDL[dz][i];
                    const int rd = 1 - (td & 1);
#pragma unroll
                    for (int j = 0; j < 2; j++) {
                        if (j >= TDN[dy]) continue;  // compile-time
                        const int th = TDL[dy][j];
                        const int rh = 1 - (th & 1);
                        const float* wt = wc + (td * 4 + th) * 4 * COVEC;
#pragma unroll
                        for (int tw = 0; tw < 4; tw++) {
                            const int rw = 1 - (tw & 1);
                            const int dx = (rw + 3 - tw) >> 1;
                            const u64* wv = (const u64*)(wt + tw * COVEC);
                            u64 wr[CP];
                            if (CP == 2) {
                                ulonglong2 wq = *(const ulonglong2*)wv; // LDS.128
                                wr[0] = wq.x; wr[CP - 1] = wq.y;
                            } else {
#pragma unroll
                                for (int c = 0; c < CP; c++) wr[c] = wv[c];
                            }
#pragma unroll
                            for (int be = 0; be < 2; be++) {
                                const u64 xv = Xe[dx + be];
                                const int o = (rd * 2 + rh) * 4 + 2 * be + rw;
#pragma unroll
                                for (int c = 0; c < CP; c++)
                                    fma2(acc[o * CP + c], xv, wr[c]);
                            }
                        }
                    }
                }
            }
        }
    }

    const int OUT2 = Out * Out;
    const size_t OUT3 = (size_t)OUT2 * Out;
    float* yo = y + ((size_t)(n * Cout + co0) * Out + 2 * bd) * OUT2
                  + (2 * bh) * Out + 4 * bq;
#pragma unroll
    for (int c = 0; c < CP; c++) {
#pragma unroll
        for (int rd = 0; rd < 2; rd++)
#pragma unroll
            for (int rh = 0; rh < 2; rh++) {
                float lo[4], hi[4];
#pragma unroll
                for (int j = 0; j < 4; j++) {
                    up2(acc[((rd * 2 + rh) * 4 + j) * CP + c], lo[j], hi[j]);
                    if (ACT == 1) { lo[j] = fmaxf(lo[j], 0.f); hi[j] = fmaxf(hi[j], 0.f); }
                }
                float* p0 = yo + (size_t)(2 * c) * OUT3 + rd * OUT2 + rh * Out;
                *(float4*)p0          = make_float4(lo[0], lo[1], lo[2], lo[3]);
                *(float4*)(p0 + OUT3) = make_float4(hi[0], hi[1], hi[2], hi[3]);
            }
    }
}

// ===========================================================================
// dec3 special: transposed conv, CIN=16 -> Cout=1, sigmoid. One thread =
// TWO adjacent w input-bases -> 2x2x4 outputs; w-output pair (rw0, rw1)
// packed per base:
//   acc(rw0,rw1) += dup(x[beta+1])       * (w[tw=1], w[tw=2])
//                +  (x[beta], x[beta+2]) * (w[tw=3], w[tw=0])
// ROW-WISE; packed weight table (512 u64) in smem, read as LDS.128 pairs.
// ===========================================================================
__global__ void __launch_bounds__(256, 2)
convT_c1_sig(const float* __restrict__ x,
             const float* __restrict__ w,   // [16][1][4][4][4]
             const float* __restrict__ bias,
             float* __restrict__ y,
             int In, int Out)
{
    constexpr int CIN = 16;
    extern __shared__ float smf[];
    u64* ws2 = (u64*)smf; // [CIN][16 (td*4+th)][2]
    const int n = blockIdx.z;

    for (int e = threadIdx.x; e < CIN * 16 * 2; e += blockDim.x) {
        int pr = e & 1;
        int tt = (e >> 1) & 15;      // td*4+th
        int ci = e >> 5;
        const float* wb = w + ci * 64 + tt * 4; // [tw]
        ws2[e] = pr ? pk2(wb[3], wb[0]) : pk2(wb[1], wb[2]);
    }
    __syncthreads();

    const int BQ = In >> 1; // = 32
    const int pos = blockIdx.x * blockDim.x + threadIdx.x;
    const int bq = pos % BQ;
    const int bh = (pos / BQ) % In;
    const int bd = pos / (BQ * In);
    const int bw0 = 2 * bq;

    bool pd[3], ph[3];
    pd[0] = (bd > 0); pd[1] = true; pd[2] = (bd < In - 1);
    ph[0] = (bh > 0); ph[1] = true; ph[2] = (bh < In - 1);
    const bool pc0 = (bq > 0);
    const bool pc3 = (bq < BQ - 1);

    const float bv = __ldg(bias);
    u64 acc[8]; // [(rd*2+rh)*2 + beta], each packs (rw0, rw1)
#pragma unroll
    for (int o = 0; o < 8; o++) acc[o] = dup2(bv);

    const int TDL[3][2] = {{3, 0}, {1, 2}, {0, 0}};
    const int TDN[3]    = {1, 2, 1};

    const int IN2 = In * In;
    const size_t IN3 = (size_t)IN2 * In;
    const float* xn = x + (size_t)n * CIN * IN3;

    for (int ci = 0; ci < CIN; ci++) {
        const float* xc = xn + ci * IN3 + (bh - 1) * In + (bw0 - 1);
        const u64* wt = ws2 + ci * 32;
#pragma unroll
        for (int dz = 0; dz < 3; dz++) {
#pragma unroll
            for (int dy = 0; dy < 3; dy++) {
                const bool pr = pd[dz] && ph[dy];
                const float* row = xc + (bd + dz - 1) * IN2 + dy * In;
                float2 f2 = pr ? __ldg((const float2*)(row + 1)) : make_float2(0.f, 0.f);
                float c0s = __shfl_up_sync(0xffffffffu, f2.y, 1);
                float c3s = __shfl_down_sync(0xffffffffu, f2.x, 1);
                float xv0 = (pr && pc0) ? c0s : 0.f;
                float xv3 = (pr && pc3) ? c3s : 0.f;
                u64 xd0  = dup2(f2.x);
                u64 xd1  = dup2(f2.y);
                u64 xcr0 = pk2(xv0, f2.y);
                u64 xcr1 = pk2(f2.x, xv3);

#pragma unroll
                for (int i = 0; i < 2; i++) {
                    if (i >= TDN[dz]) continue;
                    const int td = TDL[dz][i];
                    const int rd = 1 - (td & 1);
#pragma unroll
                    for (int j = 0; j < 2; j++) {
                        if (j >= TDN[dy]) continue;
                        const int th = TDL[dy][j];
                        const int rh = 1 - (th & 1);
                        const ulonglong2 wq =
                            *(const ulonglong2*)(wt + (td * 4 + th) * 2); // LDS.128
                        const int o = (rd * 2 + rh) * 2;
                        fma2(acc[o + 0], xd0,  wq.x);
                        fma2(acc[o + 0], xcr0, wq.y);
                        fma2(acc[o + 1], xd1,  wq.x);
                        fma2(acc[o + 1], xcr1, wq.y);
                    }
                }
            }
        }
    }

    const int OUT2 = Out * Out;
    float* yo = y + ((size_t)n * Out + 2 * bd) * OUT2 + (2 * bh) * Out + 4 * bq;
#pragma unroll
    for (int rd = 0; rd < 2; rd++)
#pragma unroll
        for (int rh = 0; rh < 2; rh++) {
            float4 r;
            float a, b;
            up2(acc[(rd * 2 + rh) * 2 + 0], a, b);
            r.x = 1.f / (1.f + __expf(-a));
            r.y = 1.f / (1.f + __expf(-b));
            up2(acc[(rd * 2 + rh) * 2 + 1], a, b);
            r.z = 1.f / (1.f + __expf(-a));
            r.w = 1.f / (1.f + __expf(-b));
            *(float4*)(yo + rd * OUT2 + rh * Out) = r;
        }
}

// ===========================================================================
// Vector quantization: argmin_k (||c_k||^2 - 2 z.c_k), f32x2 dot products,
// k processed 2 at a time (4 independent fma2 chains).
// 512 threads/block, 128 positions/block; 512-code scan split across 4
// threads per position (ascending quarters). Strict '<' combine preserves
// jnp.argmin first-minimum tie-break.
// ===========================================================================
__global__ void vq_kernel(const float* __restrict__ ze,
                          const float* __restrict__ cb,
                          float* __restrict__ quant)
{
    extern __shared__ float s[];
    float* scb   = s;                   // [512*64]
    float* snorm = scb + 512 * 64;      // [512]
    float* sbest = snorm + 512;         // [4][128]
    int*   sbidx = (int*)(sbest + 512); // [4][128]

    for (int e = threadIdx.x; e < 512 * 64; e += blockDim.x) scb[e] = cb[e];
    __syncthreads();
    for (int k = threadIdx.x; k < 512; k += blockDim.x) {
        float a = 0.f;
#pragma unroll
        for (int j = 0; j < 64; j++) { float c = scb[k * 64 + j]; a = fmaf(c, c, a); }
        snorm[k] = a;
    }
    __syncthreads();

    const int lp = threadIdx.x & 127;
    const int q  = threadIdx.x >> 7;        // quarter 0..3
    const int p  = blockIdx.x * 128 + lp;   // 0..16383
    const int n  = p >> 12;
    const int sp = p & 4095;

    const float* zp = ze + (size_t)(n * 64) * 4096 + sp;
    u64 z2[32];
#pragma unroll
    for (int j = 0; j < 32; j++)
        z2[j] = pk2(__ldg(zp + (2 * j) * 4096), __ldg(zp + (2 * j + 1) * 4096));

    const int k0 = q * 128;
    float best = 3.4e38f;
    int   bi   = k0;
    for (int k = k0; k < k0 + 128; k += 2) {
        const ulonglong2* cA = (const ulonglong2*)(scb + k * 64);
        const ulonglong2* cB = (const ulonglong2*)(scb + (k + 1) * 64);
        u64 a0 = 0ull, a1 = 0ull, b0 = 0ull, b1 = 0ull;
#pragma unroll
        for (int j = 0; j < 16; j++) {
            ulonglong2 ca = cA[j];
            ulonglong2 cbv = cB[j];
            fma2(a0, z2[2 * j + 0], ca.x);
            fma2(a1, z2[2 * j + 1], ca.y);
            fma2(b0, z2[2 * j + 0], cbv.x);
            fma2(b1, z2[2 * j + 1], cbv.y);
        }
        float s0, s1, s2, s3;
        up2(a0, s0, s1); up2(a1, s2, s3);
        float scoreA = snorm[k] - 2.f * ((s0 + s1) + (s2 + s3));
        up2(b0, s0, s1); up2(b1, s2, s3);
        float scoreB = snorm[k + 1] - 2.f * ((s0 + s1) + (s2 + s3));
        if (scoreA < best) { best = scoreA; bi = k; }
        if (scoreB < best) { best = scoreB; bi = k + 1; }
    }

    sbest[q * 128 + lp] = best;
    sbidx[q * 128 + lp] = bi;
    __syncthreads();
    if (q == 0) {
#pragma unroll
        for (int qq = 1; qq < 4; qq++) {
            float ob = sbest[qq * 128 + lp];
            if (ob < best) { best = ob; bi = sbidx[qq * 128 + lp]; }
        }
        sbidx[lp] = bi;
    }
    __syncthreads();

    const int fi = sbidx[lp];
    float* qp = quant + (size_t)(n * 64) * 4096 + sp;
#pragma unroll
    for (int j = 0; j < 16; j++) {
        int jj = q * 16 + j;
        qp[(size_t)jj * 4096] = scb[fi * 64 + jj];
    }
}

// ===========================================================================
// Launch
// ===========================================================================
extern "C" void kernel_launch(void* const* d_in, const int* in_sizes, int n_in,
                              void* d_out, int out_size)
{
    const float* x   = (const float*)d_in[0];
    const float* w1  = (const float*)d_in[1];
    const float* b1  = (const float*)d_in[2];
    const float* w2  = (const float*)d_in[3];
    const float* b2  = (const float*)d_in[4];
    const float* w3  = (const float*)d_in[5];
    const float* b3  = (const float*)d_in[6];
    const float* cb  = (const float*)d_in[7];
    const float* dw1 = (const float*)d_in[8];
    const float* db1 = (const float*)d_in[9];
    const float* dw2 = (const float*)d_in[10];
    const float* db2 = (const float*)d_in[11];
    const float* dw3 = (const float*)d_in[12];
    const float* db3 = (const float*)d_in[13];

    float* out   = (float*)d_out;
    const int XHAT_N = in_sizes[0];           // 4*1*128^3 = 8388608
    const int Z_N    = 4 * 64 * 16 * 16 * 16; // 1048576
    float* xhat  = out;
    float* quant = out + XHAT_N;
    float* ze    = out + XHAT_N + Z_N;

    float *h1, *h2;
    cudaGetSymbolAddress((void**)&h1, g_h1);
    cudaGetSymbolAddress((void**)&h2, g_h2);

    const int VQ_SMEM = (512 * 64 + 512 + 512 + 512) * 4; // 137216 B

    // opt-in to >48KB dynamic smem (idempotent)
    cudaFuncSetAttribute(convT_blk<64, 4, 1>,
                         cudaFuncAttributeMaxDynamicSharedMemorySize, 80 * 1024);
    cudaFuncSetAttribute(vq_kernel,
                         cudaFuncAttributeMaxDynamicSharedMemorySize, VQ_SMEM);

    const int T = 256;

    // enc1: 1->16, 128 -> 64, relu. bases 32*32*16 = 16384, COVEC=4
    {
        dim3 g(16384 / T, 16 / 4, 4);
        conv_s2_blk<1, 4, 1><<<g, T, 1 * 64 * 4 * 4>>>(x, w1, b1, h1, 128, 64, 16);
    }
    // enc2: 16->32, 64 -> 32, relu. bases 16*16*8 = 2048, COVEC=4
    {
        dim3 g(2048 / T, 32 / 4, 4);
        conv_s2_blk<16, 4, 1><<<g, T, 16 * 64 * 4 * 4>>>(h1, w2, b2, h2, 64, 32, 32);
    }
    // enc3: 32->64, 32 -> 16, no act -> z_e. bases 8*8*4 = 256, COVEC=2
    {
        dim3 g(256 / T, 64 / 2, 4);
        conv_s2_blk<32, 2, 0><<<g, T, 32 * 64 * 2 * 4>>>(h2, w3, b3, ze, 32, 16, 64);
    }
    // vq: z_e -> quantized
    {
        vq_kernel<<<128, 512, VQ_SMEM>>>(ze, cb, quant);
    }
    // dec1: 64->32, 16 -> 32, relu. bases 8*16*16 = 2048. smem 64KB
    {
        dim3 g(2048 / T, 32 / 4, 4);
        convT_blk<64, 4, 1><<<g, T, 64 * 64 * 4 * 4>>>(quant, dw1, db1, h2, 16, 32, 32);
    }
    // dec2: 32->16, 32 -> 64, relu. bases 16*32*32 = 16384. smem 32KB
    {
        dim3 g(16384 / T, 16 / 4, 4);
        convT_blk<32, 4, 1><<<g, T, 32 * 64 * 4 * 4>>>(h2, dw2, db2, h1, 32, 64, 16);
    }
    // dec3: 16->1, 64 -> 128, sigmoid. base-pair grid 32*64*64 = 131072
    {
        dim3 g(131072 / T, 1, 4);
        convT_c1_sig<<<g, T, 16 * 16 * 2 * 8>>>(h1, dw3, db3, xhat, 64, 128);
    }
    (void)n_in; (void)out_size;
}

// round 16
// speedup vs baseline: 1.2666x; 1.2666x over previous
#include <cuda_runtime.h>
#include <math.h>

// ---------------------------------------------------------------------------
// VQ-VAE 3D forward (R16): R12 structure (plane/cube-batched loads, 64
// weight-LDS.128/ci) with occupancy raised to 12 warps/SM:
//  - strided conv: plane stored as floats, dup-packed per row-pair (v, v+2)
//    (shares weight LDS across rh), ~150 regs, launch_bounds(128,3)
//  - transposed conv: R12 code, 128-thread blocks, launch_bounds(128,3)
// Output layout in d_out (float): [x_hat (4*1*128^3) | quantized | z_e]
// ---------------------------------------------------------------------------

typedef unsigned long long u64;

__device__ __forceinline__ u64 pk2(float lo, float hi) {
    u64 r; asm("mov.b64 %0, {%1, %2};" : "=l"(r) : "f"(lo), "f"(hi)); return r;
}
__device__ __forceinline__ u64 dup2(float v) { return pk2(v, v); }
__device__ __forceinline__ void fma2(u64& d, u64 a, u64 b) {
    asm("fma.rn.f32x2 %0, %1, %2, %0;" : "+l"(d) : "l"(a), "l"(b));
}
__device__ __forceinline__ void up2(u64 v, float& a, float& b) {
    asm("mov.b64 {%0, %1}, %2;" : "=f"(a), "=f"(b) : "l"(v));
}

// scratch (no allocations allowed) -- reused across stages
__device__ __align__(16) float g_h1[4 * 16 * 64 * 64 * 64]; // conv1 out / dec2 out
__device__ __align__(16) float g_h2[4 * 32 * 32 * 32 * 32]; // conv2 out / dec1 out

// ===========================================================================
// Strided conv3d, k=4 s=2 p=1. One thread = 2(od) x 2(oh) x 4(ow) outputs x
// COVEC=2 channels (channel-paired f32x2 accumulators).
// Plane (6x10) loaded BATCHED as floats (MLP ~12); consumption by row-pairs
// (v, v+2) which share ah=v so each weight LDS.128 serves both rh values
// (64 LDS.128 per ci, same as R12). Rows dup-packed transiently per pair.
// Row load: 2 aligned float4; edge cols via neighbor-lane shfl (BQ | 32,
// shfl-invalid lanes are exactly the zero-padded ones).
// ACT: 0 none, 1 relu
// ===========================================================================
template <int CIN, int ACT>
__global__ void __launch_bounds__(128, 3)
conv_s2_blk(const float* __restrict__ x,
            const float* __restrict__ w,   // [Cout][CIN][4][4][4]
            const float* __restrict__ bias,
            float* __restrict__ y,
            int Din, int Dout, int Cout)
{
    constexpr int COVEC = 2;
    extern __shared__ float ws[]; // [CIN*64][COVEC] interleaved
    const int co0 = blockIdx.y * COVEC;
    const int n   = blockIdx.z;

    const int WTOT = CIN * 64 * COVEC;
    for (int e = threadIdx.x; e < WTOT; e += blockDim.x) {
        int c  = e % COVEC;
        int r  = e / COVEC;          // ci*64 + tap
        int ci = r >> 6, t = r & 63;
        ws[e] = w[((co0 + c) * CIN + ci) * 64 + t];
    }
    __syncthreads();

    const int B   = Dout >> 1;  // oh/od bases
    const int BQ  = Dout >> 2;  // ow quads (4 | BQ | 32 for all layers)
    const int pos = blockIdx.x * blockDim.x + threadIdx.x;
    const int bq = pos % BQ;
    const int bh = (pos / BQ) % B;
    const int bd = pos / (BQ * B);

    const int zb = 4 * bd - 1, yb = 4 * bh - 1, xb0 = 8 * bq - 1;
    bool pz[6], py[6];
#pragma unroll
    for (int u = 0; u < 6; u++) {
        pz[u] = (unsigned)(zb + u) < (unsigned)Din;
        py[u] = (unsigned)(yb + u) < (unsigned)Din;
    }
    const bool px0 = (bq > 0);
    const bool px9 = (bq < BQ - 1);

    const u64 binit = pk2(bias[co0], bias[co0 + 1]);
    u64 acc[16]; // [(rd*2+rh)*4 + rw]
#pragma unroll
    for (int o = 0; o < 16; o++) acc[o] = binit;

    const int DIN2 = Din * Din;
    const float* xn = x + (size_t)n * CIN * Din * DIN2;

    for (int ci = 0; ci < CIN; ci++) {
        const float* xc = xn + (size_t)ci * Din * DIN2;
        const float* wc = ws + ci * 64 * COVEC;
#pragma unroll
        for (int u = 0; u < 6; u++) {
            // ---- batched plane load (z = zb+u), floats ----
            float F[60];
            const float* rowz = xc + (zb + u) * DIN2 + yb * Din + xb0;
#pragma unroll
            for (int v = 0; v < 6; v++) {
                const bool pr = pz[u] && py[v];
                const float* row = rowz + v * Din;
                float4 fa = pr ? __ldg((const float4*)(row + 1))
                               : make_float4(0.f, 0.f, 0.f, 0.f);
                float4 fb = pr ? __ldg((const float4*)(row + 5))
                               : make_float4(0.f, 0.f, 0.f, 0.f);
                float x0s = __shfl_up_sync(0xffffffffu, fb.w, 1);   // col 8bq-1
                float x9s = __shfl_down_sync(0xffffffffu, fa.x, 1); // col 8bq+8
                float* Fv = F + v * 10;
                Fv[0] = (pr && px0) ? x0s : 0.f;
                Fv[1] = fa.x; Fv[2] = fa.y; Fv[3] = fa.z; Fv[4] = fa.w;
                Fv[5] = fb.x; Fv[6] = fb.y; Fv[7] = fb.z; Fv[8] = fb.w;
                Fv[9] = (pr && px9) ? x9s : 0.f;
            }

            // ---- consume by row-pairs (ah = vp): rows vp (rh=0), vp+2 (rh=1)
#pragma unroll
            for (int vp = 0; vp < 4; vp++) {
                u64 R0[10], R1[10];
#pragma unroll
                for (int i = 0; i < 10; i++) {
                    R0[i] = dup2(F[vp * 10 + i]);
                    R1[i] = dup2(F[(vp + 2) * 10 + i]);
                }
#pragma unroll
                for (int rd = 0; rd < 2; rd++) {
                    const int a_d = u - 2 * rd;
                    if (a_d < 0 || a_d > 3) continue;   // compile-time
                    const int o0 = (rd * 2 + 0) * 4;
                    const int o1 = (rd * 2 + 1) * 4;
#pragma unroll
                    for (int awp = 0; awp < 2; awp++) {
                        const ulonglong2 wq = *(const ulonglong2*)
                            (wc + (a_d * 16 + vp * 4 + 2 * awp) * COVEC);
#pragma unroll
                        for (int rw = 0; rw < 4; rw++) {
                            fma2(acc[o0 + rw], R0[2 * rw + 2 * awp],     wq.x);
                            fma2(acc[o0 + rw], R0[2 * rw + 2 * awp + 1], wq.y);
                            fma2(acc[o1 + rw], R1[2 * rw + 2 * awp],     wq.x);
                            fma2(acc[o1 + rw], R1[2 * rw + 2 * awp + 1], wq.y);
                        }
                    }
                }
            }
        }
    }

    const int OUT2 = Dout * Dout;
    const size_t OUT3 = (size_t)OUT2 * Dout;
    float* yo = y + ((size_t)(n * Cout + co0) * Dout + 2 * bd) * OUT2
                  + (2 * bh) * Dout + 4 * bq;
#pragma unroll
    for (int rd = 0; rd < 2; rd++)
#pragma unroll
        for (int rh = 0; rh < 2; rh++) {
            float lo[4], hi[4];
#pragma unroll
            for (int rw = 0; rw < 4; rw++) {
                up2(acc[(rd * 2 + rh) * 4 + rw], lo[rw], hi[rw]);
                if (ACT == 1) { lo[rw] = fmaxf(lo[rw], 0.f); hi[rw] = fmaxf(hi[rw], 0.f); }
            }
            float* p0 = yo + rd * OUT2 + rh * Dout;
            *(float4*)p0          = make_float4(lo[0], lo[1], lo[2], lo[3]);
            *(float4*)(p0 + OUT3) = make_float4(hi[0], hi[1], hi[2], hi[3]);
        }
}

// ===========================================================================
// Transposed conv3d, k=4 s=2 p=1 (R12 structure: batched 3x3x4 cube, MLP~9).
// One thread = TWO adjacent w input-bases -> 2(od) x 2(oh) x 4(ow) outputs x
// COVEC channels (channel-paired f32x2, CP = COVEC/2).
// tap t -> (r, delta): t=0:(1,+1) t=1:(0,0) t=2:(1,0) t=3:(0,-1);
// cube index dz = (r + 3 - t) >> 1; for base beta the source col is dx+beta.
// Row load: one float2; edge cols via shfl from neighbor lanes (BQ | 32).
// Weight read: one LDS.128 per tap when CP==2.
// Weights: PyTorch ConvTranspose layout [CIN][Cout][4][4][4].
// ACT: 0 none, 1 relu
// ===========================================================================
template <int CIN, int COVEC, int ACT>
__global__ void __launch_bounds__(128, 3)
convT_blk(const float* __restrict__ x,
          const float* __restrict__ w,
          const float* __restrict__ bias,
          float* __restrict__ y,
          int In, int Out, int Cout)
{
    static_assert(COVEC % 2 == 0, "COVEC even");
    constexpr int CP = COVEC / 2;
    extern __shared__ float ws[]; // [CIN*64][COVEC]
    const int co0 = blockIdx.y * COVEC;
    const int n   = blockIdx.z;

    const int WTOT = CIN * 64 * COVEC;
    for (int e = threadIdx.x; e < WTOT; e += blockDim.x) {
        int c  = e % COVEC;
        int r  = e / COVEC;
        int ci = r >> 6, t = r & 63;
        ws[e] = w[((size_t)ci * Cout + co0 + c) * 64 + t];
    }
    __syncthreads();

    const int BQ  = In >> 1; // w base-pairs per dim (8/16/32 — divides 32)
    const int pos = blockIdx.x * blockDim.x + threadIdx.x;
    const int bq = pos % BQ;
    const int bh = (pos / BQ) % In;
    const int bd = pos / (BQ * In);
    const int bw0 = 2 * bq;

    bool pd[3], ph[3];
    pd[0] = (bd > 0); pd[1] = true; pd[2] = (bd < In - 1);
    ph[0] = (bh > 0); ph[1] = true; ph[2] = (bh < In - 1);
    const bool pc0 = (bq > 0);
    const bool pc3 = (bq < BQ - 1);

    u64 acc[16 * CP]; // [((rd*2+rh)*4 + (2*beta+rw)) * CP + c]
#pragma unroll
    for (int o = 0; o < 16; o++)
#pragma unroll
        for (int c = 0; c < CP; c++)
            acc[o * CP + c] = pk2(bias[co0 + 2 * c], bias[co0 + 2 * c + 1]);

    const int IN2 = In * In;
    const size_t IN3 = (size_t)IN2 * In;
    const float* xn = x + (size_t)n * CIN * IN3;

    for (int ci = 0; ci < CIN; ci++) {
        const float* xc = xn + ci * IN3;
        const float* wc = ws + ci * 64 * COVEC;

        u64 X[36]; // dup-packed 3x3x4 cube: [(dz*3+dy)*4 + cc], cc = col - (bw0-1)
#pragma unroll
        for (int dz = 0; dz < 3; dz++)
#pragma unroll
            for (int dy = 0; dy < 3; dy++) {
                const bool pr = pd[dz] && ph[dy];
                const float* row = xc + (bd + dz - 1) * IN2 + (bh + dy - 1) * In + (bw0 - 1);
                float2 f2 = pr ? __ldg((const float2*)(row + 1)) : make_float2(0.f, 0.f);
                float c0s = __shfl_up_sync(0xffffffffu, f2.y, 1);   // col bw0-1
                float c3s = __shfl_down_sync(0xffffffffu, f2.x, 1); // col bw0+2
                float c0 = (pr && pc0) ? c0s : 0.f;
                float c3 = (pr && pc3) ? c3s : 0.f;
                u64* Xe = X + (dz * 3 + dy) * 4;
                Xe[0] = dup2(c0);
                Xe[1] = dup2(f2.x);
                Xe[2] = dup2(f2.y);
                Xe[3] = dup2(c3);
            }

#pragma unroll
        for (int td = 0; td < 4; td++) {
            const int rd = 1 - (td & 1);
            const int dz = (rd + 3 - td) >> 1;
#pragma unroll
            for (int th = 0; th < 4; th++) {
                const int rh = 1 - (th & 1);
                const int dy = (rh + 3 - th) >> 1;
                const u64* Xe = X + (dz * 3 + dy) * 4;
#pragma unroll
                for (int tw = 0; tw < 4; tw++) {
                    const int rw = 1 - (tw & 1);
                    const int dx = (rw + 3 - tw) >> 1;
                    const u64* wv = (const u64*)(wc + ((td * 4 + th) * 4 + tw) * COVEC);
                    u64 wr[CP];
                    if (CP == 2) {
                        ulonglong2 wq = *(const ulonglong2*)wv; // LDS.128
                        wr[0] = wq.x; wr[CP - 1] = wq.y;
                    } else {
#pragma unroll
                        for (int c = 0; c < CP; c++) wr[c] = wv[c];
                    }
#pragma unroll
                    for (int be = 0; be < 2; be++) {
                        const u64 xv = Xe[dx + be];
                        const int o = (rd * 2 + rh) * 4 + 2 * be + rw;
#pragma unroll
                        for (int c = 0; c < CP; c++)
                            fma2(acc[o * CP + c], xv, wr[c]);
                    }
                }
            }
        }
    }

    const int OUT2 = Out * Out;
    const size_t OUT3 = (size_t)OUT2 * Out;
    float* yo = y + ((size_t)(n * Cout + co0) * Out + 2 * bd) * OUT2
                  + (2 * bh) * Out + 4 * bq;
#pragma unroll
    for (int c = 0; c < CP; c++) {
#pragma unroll
        for (int rd = 0; rd < 2; rd++)
#pragma unroll
            for (int rh = 0; rh < 2; rh++) {
                float lo[4], hi[4];
#pragma unroll
                for (int j = 0; j < 4; j++) {
                    up2(acc[((rd * 2 + rh) * 4 + j) * CP + c], lo[j], hi[j]);
                    if (ACT == 1) { lo[j] = fmaxf(lo[j], 0.f); hi[j] = fmaxf(hi[j], 0.f); }
                }
                float* p0 = yo + (size_t)(2 * c) * OUT3 + rd * OUT2 + rh * Out;
                *(float4*)p0          = make_float4(lo[0], lo[1], lo[2], lo[3]);
                *(float4*)(p0 + OUT3) = make_float4(hi[0], hi[1], hi[2], hi[3]);
            }
    }
}

// ===========================================================================
// dec3 special: transposed conv, CIN=16 -> Cout=1, sigmoid. One thread =
// TWO adjacent w input-bases (3x3x4 cube) -> 2x2x4 outputs; w-output pair
// (rw0, rw1) packed per base:
//   acc(rw0,rw1) += dup(x[beta+1])       * (w[tw=1], w[tw=2])
//                +  (x[beta], x[beta+2]) * (w[tw=3], w[tw=0])
// Packed weight table (512 u64) prebuilt in smem, read as LDS.128 pairs.
// Edge cols via shfl (BQ = 32 divides 32). Output stored as float4.
// ===========================================================================
__global__ void convT_c1_sig(const float* __restrict__ x,
                             const float* __restrict__ w,   // [16][1][4][4][4]
                             const float* __restrict__ bias,
                             float* __restrict__ y,
                             int In, int Out)
{
    constexpr int CIN = 16;
    extern __shared__ float smf[];
    u64* ws2 = (u64*)smf; // [CIN][16 (td*4+th)][2]
    const int n = blockIdx.z;

    for (int e = threadIdx.x; e < CIN * 16 * 2; e += blockDim.x) {
        int pr = e & 1;
        int tt = (e >> 1) & 15;      // td*4+th
        int ci = e >> 5;
        const float* wb = w + ci * 64 + tt * 4; // [tw]
        ws2[e] = pr ? pk2(wb[3], wb[0]) : pk2(wb[1], wb[2]);
    }
    __syncthreads();

    const int BQ = In >> 1; // w base-pairs per dim (= 32)
    const int pos = blockIdx.x * blockDim.x + threadIdx.x;
    const int bq = pos % BQ;
    const int bh = (pos / BQ) % In;
    const int bd = pos / (BQ * In);
    const int bw0 = 2 * bq;

    bool pd[3], ph[3];
    pd[0] = (bd > 0); pd[1] = true; pd[2] = (bd < In - 1);
    ph[0] = (bh > 0); ph[1] = true; ph[2] = (bh < In - 1);
    const bool pc0 = (bq > 0);
    const bool pc3 = (bq < BQ - 1);

    const float bv = __ldg(bias);
    u64 acc[8]; // [(rd*2+rh)*2 + beta], each packs (rw0, rw1)
#pragma unroll
    for (int o = 0; o < 8; o++) acc[o] = dup2(bv);

    const int TD[2][2] = {{1, 3}, {0, 2}};
    const int DZ[2][2] = {{1, 0}, {2, 1}};

    const int IN2 = In * In;
    const size_t IN3 = (size_t)IN2 * In;
    const float* xn = x + (size_t)n * CIN * IN3;

    for (int ci = 0; ci < CIN; ci++) {
        const float* xc = xn + ci * IN3;
        const u64* wt = ws2 + ci * 32;

        u64 xd[9][2], xcr[9][2]; // dup / cross packs per (dz,dy)
#pragma unroll
        for (int dz = 0; dz < 3; dz++)
#pragma unroll
            for (int dy = 0; dy < 3; dy++) {
                const float* row = xc + (bd + dz - 1) * IN2 + (bh + dy - 1) * In + (bw0 - 1);
                const bool pr = pd[dz] && ph[dy];
                float2 f2 = pr ? __ldg((const float2*)(row + 1)) : make_float2(0.f, 0.f);
                float c0s = __shfl_up_sync(0xffffffffu, f2.y, 1);   // col bw0-1
                float c3s = __shfl_down_sync(0xffffffffu, f2.x, 1); // col bw0+2
                float xv0 = (pr && pc0) ? c0s : 0.f;
                float xv3 = (pr && pc3) ? c3s : 0.f;
                const int e = dz * 3 + dy;
                xd[e][0]  = dup2(f2.x);
                xd[e][1]  = dup2(f2.y);
                xcr[e][0] = pk2(xv0, f2.y);
                xcr[e][1] = pk2(f2.x, xv3);
            }

#pragma unroll
        for (int rd = 0; rd < 2; rd++)
#pragma unroll
            for (int sd = 0; sd < 2; sd++) {
                const int td = TD[rd][sd], dz = DZ[rd][sd];
#pragma unroll
                for (int rh = 0; rh < 2; rh++)
#pragma unroll
                    for (int sh = 0; sh < 2; sh++) {
                        const int th = TD[rh][sh], dy = DZ[rh][sh];
                        const ulonglong2 wq =
                            *(const ulonglong2*)(wt + (td * 4 + th) * 2); // LDS.128
                        const int e = dz * 3 + dy;
#pragma unroll
                        for (int be = 0; be < 2; be++) {
                            const int o = (rd * 2 + rh) * 2 + be;
                            fma2(acc[o], xd[e][be], wq.x);
                            fma2(acc[o], xcr[e][be], wq.y);
                        }
                    }
            }
    }

    const int OUT2 = Out * Out;
    float* yo = y + ((size_t)n * Out + 2 * bd) * OUT2 + (2 * bh) * Out + 4 * bq;
#pragma unroll
    for (int rd = 0; rd < 2; rd++)
#pragma unroll
        for (int rh = 0; rh < 2; rh++) {
            float4 r;
            float a, b;
            up2(acc[(rd * 2 + rh) * 2 + 0], a, b);
            r.x = 1.f / (1.f + __expf(-a));
            r.y = 1.f / (1.f + __expf(-b));
            up2(acc[(rd * 2 + rh) * 2 + 1], a, b);
            r.z = 1.f / (1.f + __expf(-a));
            r.w = 1.f / (1.f + __expf(-b));
            *(float4*)(yo + rd * OUT2 + rh * Out) = r;
        }
}

// ===========================================================================
// Vector quantization: argmin_k (||c_k||^2 - 2 z.c_k), f32x2 dot products,
// k processed 2 at a time (4 independent fma2 chains).
// 512 threads/block, 128 positions/block; 512-code scan split across 4
// threads per position (ascending quarters). Strict '<' combine preserves
// jnp.argmin first-minimum tie-break.
// ===========================================================================
__global__ void vq_kernel(const float* __restrict__ ze,
                          const float* __restrict__ cb,
                          float* __restrict__ quant)
{
    extern __shared__ float s[];
    float* scb   = s;                   // [512*64]
    float* snorm = scb + 512 * 64;      // [512]
    float* sbest = snorm + 512;         // [4][128]
    int*   sbidx = (int*)(sbest + 512); // [4][128]

    for (int e = threadIdx.x; e < 512 * 64; e += blockDim.x) scb[e] = cb[e];
    __syncthreads();
    for (int k = threadIdx.x; k < 512; k += blockDim.x) {
        float a = 0.f;
#pragma unroll
        for (int j = 0; j < 64; j++) { float c = scb[k * 64 + j]; a = fmaf(c, c, a); }
        snorm[k] = a;
    }
    __syncthreads();

    const int lp = threadIdx.x & 127;
    const int q  = threadIdx.x >> 7;        // quarter 0..3
    const int p  = blockIdx.x * 128 + lp;   // 0..16383
    const int n  = p >> 12;
    const int sp = p & 4095;

    const float* zp = ze + (size_t)(n * 64) * 4096 + sp;
    u64 z2[32];
#pragma unroll
    for (int j = 0; j < 32; j++)
        z2[j] = pk2(__ldg(zp + (2 * j) * 4096), __ldg(zp + (2 * j + 1) * 4096));

    const int k0 = q * 128;
    float best = 3.4e38f;
    int   bi   = k0;
    for (int k = k0; k < k0 + 128; k += 2) {
        const ulonglong2* cA = (const ulonglong2*)(scb + k * 64);
        const ulonglong2* cB = (const ulonglong2*)(scb + (k + 1) * 64);
        u64 a0 = 0ull, a1 = 0ull, b0 = 0ull, b1 = 0ull;
#pragma unroll
        for (int j = 0; j < 16; j++) {
            ulonglong2 ca = cA[j];
            ulonglong2 cbv = cB[j];
            fma2(a0, z2[2 * j + 0], ca.x);
            fma2(a1, z2[2 * j + 1], ca.y);
            fma2(b0, z2[2 * j + 0], cbv.x);
            fma2(b1, z2[2 * j + 1], cbv.y);
        }
        float s0, s1, s2, s3;
        up2(a0, s0, s1); up2(a1, s2, s3);
        float scoreA = snorm[k] - 2.f * ((s0 + s1) + (s2 + s3));
        up2(b0, s0, s1); up2(b1, s2, s3);
        float scoreB = snorm[k + 1] - 2.f * ((s0 + s1) + (s2 + s3));
        if (scoreA < best) { best = scoreA; bi = k; }
        if (scoreB < best) { best = scoreB; bi = k + 1; }
    }

    sbest[q * 128 + lp] = best;
    sbidx[q * 128 + lp] = bi;
    __syncthreads();
    if (q == 0) {
#pragma unroll
        for (int qq = 1; qq < 4; qq++) {
            float ob = sbest[qq * 128 + lp];
            if (ob < best) { best = ob; bi = sbidx[qq * 128 + lp]; }
        }
        sbidx[lp] = bi;
    }
    __syncthreads();

    const int fi = sbidx[lp];
    float* qp = quant + (size_t)(n * 64) * 4096 + sp;
#pragma unroll
    for (int j = 0; j < 16; j++) {
        int jj = q * 16 + j;
        qp[(size_t)jj * 4096] = scb[fi * 64 + jj];
    }
}

// ===========================================================================
// Launch
// ===========================================================================
extern "C" void kernel_launch(void* const* d_in, const int* in_sizes, int n_in,
                              void* d_out, int out_size)
{
    const float* x   = (const float*)d_in[0];
    const float* w1  = (const float*)d_in[1];
    const float* b1  = (const float*)d_in[2];
    const float* w2  = (const float*)d_in[3];
    const float* b2  = (const float*)d_in[4];
    const float* w3  = (const float*)d_in[5];
    const float* b3  = (const float*)d_in[6];
    const float* cb  = (const float*)d_in[7];
    const float* dw1 = (const float*)d_in[8];
    const float* db1 = (const float*)d_in[9];
    const float* dw2 = (const float*)d_in[10];
    const float* db2 = (const float*)d_in[11];
    const float* dw3 = (const float*)d_in[12];
    const float* db3 = (const float*)d_in[13];

    float* out   = (float*)d_out;
    const int XHAT_N = in_sizes[0];           // 4*1*128^3 = 8388608
    const int Z_N    = 4 * 64 * 16 * 16 * 16; // 1048576
    float* xhat  = out;
    float* quant = out + XHAT_N;
    float* ze    = out + XHAT_N + Z_N;

    float *h1, *h2;
    cudaGetSymbolAddress((void**)&h1, g_h1);
    cudaGetSymbolAddress((void**)&h2, g_h2);

    const int VQ_SMEM = (512 * 64 + 512 + 512 + 512) * 4; // 137216 B

    // opt-in to >48KB dynamic smem (idempotent)
    cudaFuncSetAttribute(convT_blk<64, 4, 1>,
                         cudaFuncAttributeMaxDynamicSharedMemorySize, 80 * 1024);
    cudaFuncSetAttribute(vq_kernel,
                         cudaFuncAttributeMaxDynamicSharedMemorySize, VQ_SMEM);

    const int T = 128;

    // enc1: 1->16, 128 -> 64, relu. bases 32*32*16 = 16384, COVEC=2
    {
        dim3 g(16384 / T, 16 / 2, 4);
        conv_s2_blk<1, 1><<<g, T, 1 * 64 * 2 * 4>>>(x, w1, b1, h1, 128, 64, 16);
    }
    // enc2: 16->32, 64 -> 32, relu. bases 16*16*8 = 2048, COVEC=2
    {
        dim3 g(2048 / T, 32 / 2, 4);
        conv_s2_blk<16, 1><<<g, T, 16 * 64 * 2 * 4>>>(h1, w2, b2, h2, 64, 32, 32);
    }
    // enc3: 32->64, 32 -> 16, no act -> z_e. bases 8*8*4 = 256, COVEC=2
    {
        dim3 g(256 / T, 64 / 2, 4);
        conv_s2_blk<32, 0><<<g, T, 32 * 64 * 2 * 4>>>(h2, w3, b3, ze, 32, 16, 64);
    }
    // vq: z_e -> quantized
    {
        vq_kernel<<<128, 512, VQ_SMEM>>>(ze, cb, quant);
    }
    // dec1: 64->32, 16 -> 32, relu. bases 8*16*16 = 2048. smem 64KB
    {
        dim3 g(2048 / T, 32 / 4, 4);
        convT_blk<64, 4, 1><<<g, T, 64 * 64 * 4 * 4>>>(quant, dw1, db1, h2, 16, 32, 32);
    }
    // dec2: 32->16, 32 -> 64, relu. bases 16*32*32 = 16384. smem 32KB
    {
        dim3 g(16384 / T, 16 / 4, 4);
        convT_blk<32, 4, 1><<<g, T, 32 * 64 * 4 * 4>>>(h2, dw2, db2, h1, 32, 64, 16);
    }
    // dec3: 16->1, 64 -> 128, sigmoid. base-pair grid 32*64*64 = 131072
    {
        dim3 g(131072 / 256, 1, 4);
        convT_c1_sig<<<g, 256, 16 * 16 * 2 * 8>>>(h1, dw3, db3, xhat, 64, 128);
    }
    (void)n_in; (void)out_size;
}